// round 2
// baseline (speedup 1.0000x reference)
#include <cuda_runtime.h>
#include <mma.h>
#include <cstdint>
#include <cstddef>

using namespace nvcuda;

#define N_NODES 8192
#define IN_C    512
#define HID_C   1024
#define OUT_C   256

// ---------------- scratch (no allocations allowed) ----------------
__device__ float g_inv[N_NODES];                 // D^{-1/2}
__device__ float g_bufA[(size_t)N_NODES * HID_C]; // C1 / C2 (raw GEMM out)
__device__ float g_Hs[(size_t)N_NODES * HID_C];   // scaled hidden pre-A
__device__ float g_H[(size_t)N_NODES * HID_C];    // relu'd hidden
__device__ float g_bufB[(size_t)N_NODES * OUT_C]; // C3 / C4
__device__ float g_Os[(size_t)N_NODES * OUT_C];   // scaled out pre-A

__device__ __forceinline__ float f2tf32(float x) {
    float r;
    asm("cvt.rna.tf32.f32 %0, %1;" : "=f"(r) : "f"(x));
    return r;
}

// ---------------- row-sum -> inv sqrt degree ----------------
__global__ void rowsum_kernel(const float* __restrict__ edge, float* __restrict__ inv) {
    const int row = blockIdx.x;
    const float4* p = reinterpret_cast<const float4*>(edge + (size_t)row * N_NODES);
    float s = 0.f;
    for (int j = threadIdx.x; j < N_NODES / 4; j += blockDim.x) {
        float4 v = p[j];
        s += (v.x + v.y) + (v.z + v.w);
    }
    #pragma unroll
    for (int o = 16; o > 0; o >>= 1) s += __shfl_down_sync(0xffffffffu, s, o);
    __shared__ float red[8];
    const int lane = threadIdx.x & 31, w = threadIdx.x >> 5;
    if (lane == 0) red[w] = s;
    __syncthreads();
    if (w == 0) {
        s = (lane < 8) ? red[lane] : 0.f;
        #pragma unroll
        for (int o = 4; o > 0; o >>= 1) s += __shfl_down_sync(0xffffffffu, s, o);
        if (lane == 0) inv[row] = (s > 0.f) ? rsqrtf(s) : 0.f;
    }
}

// ---------------- tf32 wmma GEMM: C[M,N] = A[M,K] @ op(B) ----------------
// BNMAJOR=false: B stored [N,K] row-major (weights, used as B^T)
// BNMAJOR=true : B stored [K,N] row-major (activations)
constexpr int BM = 128, BN = 128, BK = 32, BKP = 40;
constexpr int WMI = 4, WNI = 2;  // warp tile 64x32 in 16x16 wmma tiles

template <bool BNMAJOR>
__global__ __launch_bounds__(256) void gemm_tf32(
    const float* __restrict__ A, const float* __restrict__ B,
    float* __restrict__ C, int M, int N, int K)
{
    __shared__ float As[BM][BKP];
    __shared__ float Bs[BN][BKP];

    const int bm0 = blockIdx.y * BM;
    const int bn0 = blockIdx.x * BN;
    const int tid = threadIdx.x;
    const int warp = tid >> 5;
    const int wm0 = (warp >> 2) * 64;   // 2 warp rows
    const int wn0 = (warp & 3) * 32;    // 4 warp cols

    wmma::fragment<wmma::accumulator, 16, 16, 8, float> acc[WMI][WNI];
    #pragma unroll
    for (int i = 0; i < WMI; i++)
        #pragma unroll
        for (int j = 0; j < WNI; j++)
            wmma::fill_fragment(acc[i][j], 0.f);

    const int ar = tid >> 3;            // 0..31
    const int ac = (tid & 7) * 4;       // 0..28
    const int bn4 = (tid & 31) * 4;     // 0..124
    const int bk  = tid >> 5;           // 0..7

    for (int k0 = 0; k0 < K; k0 += BK) {
        // A tile: [BM][BK], global row-major, coalesced float4
        #pragma unroll
        for (int it = 0; it < 4; ++it) {
            const int row = ar + it * 32;
            float4 v = *reinterpret_cast<const float4*>(
                &A[(size_t)(bm0 + row) * K + k0 + ac]);
            float4 w = make_float4(f2tf32(v.x), f2tf32(v.y), f2tf32(v.z), f2tf32(v.w));
            *reinterpret_cast<float4*>(&As[row][ac]) = w;
        }
        if (!BNMAJOR) {
            // B [N,K] row-major -> Bs[n][k], coalesced in k
            #pragma unroll
            for (int it = 0; it < 4; ++it) {
                const int row = ar + it * 32;
                float4 v = *reinterpret_cast<const float4*>(
                    &B[(size_t)(bn0 + row) * K + k0 + ac]);
                float4 w = make_float4(f2tf32(v.x), f2tf32(v.y), f2tf32(v.z), f2tf32(v.w));
                *reinterpret_cast<float4*>(&Bs[row][ac]) = w;
            }
        } else {
            // B [K,N] row-major -> transpose into Bs[n][k], coalesced in n
            #pragma unroll
            for (int it = 0; it < 4; ++it) {
                const int k = bk + it * 8;
                float4 v = *reinterpret_cast<const float4*>(
                    &B[(size_t)(k0 + k) * N + bn0 + bn4]);
                Bs[bn4 + 0][k] = f2tf32(v.x);
                Bs[bn4 + 1][k] = f2tf32(v.y);
                Bs[bn4 + 2][k] = f2tf32(v.z);
                Bs[bn4 + 3][k] = f2tf32(v.w);
            }
        }
        __syncthreads();

        #pragma unroll
        for (int ks = 0; ks < BK / 8; ++ks) {
            wmma::fragment<wmma::matrix_a, 16, 16, 8, wmma::precision::tf32, wmma::row_major> af[WMI];
            wmma::fragment<wmma::matrix_b, 16, 16, 8, wmma::precision::tf32, wmma::col_major> bf[WNI];
            #pragma unroll
            for (int i = 0; i < WMI; i++)
                wmma::load_matrix_sync(af[i], &As[wm0 + i * 16][ks * 8], BKP);
            #pragma unroll
            for (int j = 0; j < WNI; j++)
                wmma::load_matrix_sync(bf[j], &Bs[wn0 + j * 16][ks * 8], BKP);
            #pragma unroll
            for (int i = 0; i < WMI; i++)
                #pragma unroll
                for (int j = 0; j < WNI; j++)
                    wmma::mma_sync(acc[i][j], af[i], bf[j], acc[i][j]);
        }
        __syncthreads();
    }

    #pragma unroll
    for (int i = 0; i < WMI; i++)
        #pragma unroll
        for (int j = 0; j < WNI; j++)
            wmma::store_matrix_sync(
                &C[(size_t)(bm0 + wm0 + i * 16) * N + (bn0 + wn0 + j * 16)],
                acc[i][j], N, wmma::mem_row_major);
}

// ---------------- epilogues ----------------
// out[m,n] = inv[m] * (C[m,n] + bias[n])
__global__ void epi_bias_scale(const float* __restrict__ C, const float* __restrict__ bias,
                               const float* __restrict__ inv, float* __restrict__ out, int N) {
    const int i = blockIdx.x * blockDim.x + threadIdx.x;   // float4 index
    const int m = i / (N / 4);
    const int n4 = (i % (N / 4)) * 4;
    const float s = inv[m];
    float4 c = *reinterpret_cast<const float4*>(C + (size_t)m * N + n4);
    float4 b = *reinterpret_cast<const float4*>(bias + n4);
    float4 o = make_float4(s * (c.x + b.x), s * (c.y + b.y),
                           s * (c.z + b.z), s * (c.w + b.w));
    *reinterpret_cast<float4*>(out + (size_t)m * N + n4) = o;
}

// out[m,n] = relu(inv[m] * C[m,n])
__global__ void epi_relu_scale(const float* __restrict__ C, const float* __restrict__ inv,
                               float* __restrict__ out, int N) {
    const int i = blockIdx.x * blockDim.x + threadIdx.x;
    const int m = i / (N / 4);
    const int n4 = (i % (N / 4)) * 4;
    const float s = inv[m];
    float4 c = *reinterpret_cast<const float4*>(C + (size_t)m * N + n4);
    float4 o = make_float4(fmaxf(s * c.x, 0.f), fmaxf(s * c.y, 0.f),
                           fmaxf(s * c.z, 0.f), fmaxf(s * c.w, 0.f));
    *reinterpret_cast<float4*>(out + (size_t)m * N + n4) = o;
}

// ---------------- launch ----------------
extern "C" void kernel_launch(void* const* d_in, const int* in_sizes, int n_in,
                              void* d_out, int out_size) {
    const float* point = (const float*)d_in[0];
    const float* edge  = (const float*)d_in[1];
    const float* W1    = (const float*)d_in[2];
    const float* b1    = (const float*)d_in[3];
    const float* W2    = (const float*)d_in[4];
    const float* b2    = (const float*)d_in[5];
    float* out = (float*)d_out;

    float *inv, *bufA, *Hs, *H, *bufB, *Os;
    cudaGetSymbolAddress((void**)&inv,  g_inv);
    cudaGetSymbolAddress((void**)&bufA, g_bufA);
    cudaGetSymbolAddress((void**)&Hs,   g_Hs);
    cudaGetSymbolAddress((void**)&H,    g_H);
    cudaGetSymbolAddress((void**)&bufB, g_bufB);
    cudaGetSymbolAddress((void**)&Os,   g_Os);

    // D^{-1/2}
    rowsum_kernel<<<N_NODES, 256>>>(edge, inv);

    // GEMM1: C1 = point @ W1^T   [8192,1024]
    gemm_tf32<false><<<dim3(HID_C / BN, N_NODES / BM), 256>>>(
        point, W1, bufA, N_NODES, HID_C, IN_C);
    // Hs = inv[m] * (C1 + b1)
    epi_bias_scale<<<(N_NODES * HID_C / 4) / 256, 256>>>(bufA, b1, inv, Hs, HID_C);

    // GEMM2: C2 = edge @ Hs      [8192,1024]  (dominant, 137 GFLOP)
    gemm_tf32<true><<<dim3(HID_C / BN, N_NODES / BM), 256>>>(
        edge, Hs, bufA, N_NODES, HID_C, N_NODES);
    // H = relu(inv[m] * C2)
    epi_relu_scale<<<(N_NODES * HID_C / 4) / 256, 256>>>(bufA, inv, H, HID_C);

    // GEMM3: C3 = H @ W2^T       [8192,256]
    gemm_tf32<false><<<dim3(OUT_C / BN, N_NODES / BM), 256>>>(
        H, W2, bufB, N_NODES, OUT_C, HID_C);
    // Os = inv[m] * (C3 + b2)
    epi_bias_scale<<<(N_NODES * OUT_C / 4) / 256, 256>>>(bufB, b2, inv, Os, OUT_C);

    // GEMM4: C4 = edge @ Os      [8192,256]
    gemm_tf32<true><<<dim3(OUT_C / BN, N_NODES / BM), 256>>>(
        edge, Os, bufB, N_NODES, OUT_C, N_NODES);
    // out = relu(inv[m] * C4)
    epi_relu_scale<<<(N_NODES * OUT_C / 4) / 256, 256>>>(bufB, inv, out, OUT_C);
}